// round 6
// baseline (speedup 1.0000x reference)
#include <cuda_runtime.h>
#include <cstdint>

#define BB   8192
#define TT   128
#define HID  64
#define NTH  96    // each thread owns gate rows j and j+96 (192 rows total)
#define SEQ  8     // sequences per CTA

// Precomputed input-path tables (filled by precompute_tables kernel).
__device__ float gTA[7 * 192];
__device__ float gTAS[20 * 192];
__device__ float gWbet[192];

// Packed fp32x2 FMA: d = a*b + d (FFMA2, only emitted via PTX fma.rn.f32x2)
__device__ __forceinline__ void ffma2(unsigned long long &d,
                                      unsigned long long a,
                                      unsigned long long b) {
    asm("fma.rn.f32x2 %0, %1, %2, %0;" : "+l"(d) : "l"(a), "l"(b));
}
__device__ __forceinline__ float lo32(unsigned long long v) {
    return __uint_as_float((unsigned)v);
}
__device__ __forceinline__ float hi32(unsigned long long v) {
    return __uint_as_float((unsigned)(v >> 32));
}
__device__ __forceinline__ float red2(unsigned long long v) {
    return lo32(v) + hi32(v);
}

__device__ __forceinline__ float sigm_fast(float x) {
    return __fdividef(1.f, 1.f + __expf(-x));
}
__device__ __forceinline__ float tanh_fast(float x) {
    return 1.f - 2.f * __fdividef(1.f, __expf(2.f * x) + 1.f);
}

// One block of 192 threads; thread r computes row r of all tables.
__global__ void precompute_tables(const float* __restrict__ E_actor,   // [7,8]
                                  const float* __restrict__ E_action,  // [4,8]
                                  const float* __restrict__ E_street,  // [5,4]
                                  const float* __restrict__ W_proj,    // [32,21]
                                  const float* __restrict__ b_proj,    // [32]
                                  const float* __restrict__ W_ih,      // [192,32]
                                  const float* __restrict__ b_ih)      // [192]
{
    const int r = threadIdx.x;   // 0..191
    float M[21];
    #pragma unroll
    for (int c = 0; c < 21; c++) {
        float s = 0.f;
        for (int i = 0; i < 32; i++) s += W_ih[r * 32 + i] * W_proj[i * 21 + c];
        M[c] = s;
    }
    float b0 = b_ih[r];
    for (int i = 0; i < 32; i++) b0 += W_ih[r * 32 + i] * b_proj[i];

    for (int a = 0; a < 7; a++) {
        float s = b0;
        #pragma unroll
        for (int c = 0; c < 8; c++) s += M[c] * E_actor[a * 8 + c];
        gTA[a * 192 + r] = s;
    }
    for (int ac = 0; ac < 4; ac++) {
        float sa = 0.f;
        #pragma unroll
        for (int c = 0; c < 8; c++) sa += M[8 + c] * E_action[ac * 8 + c];
        for (int st = 0; st < 5; st++) {
            float s = sa;
            #pragma unroll
            for (int c = 0; c < 4; c++) s += M[16 + c] * E_street[st * 4 + c];
            gTAS[(ac * 5 + st) * 192 + r] = s;
        }
    }
    gWbet[r] = M[20];
}

__global__ __launch_bounds__(NTH, 3)
void gru_seq_kernel(const int*  __restrict__ actor,
                    const int*  __restrict__ action,
                    const int*  __restrict__ street,
                    const float* __restrict__ bet,
                    const int*  __restrict__ mask,            // bool->int32 [B,T]
                    const float* __restrict__ W_hh,           // [192,64]
                    const float* __restrict__ b_hh,           // [192]
                    float* __restrict__ out)                  // [B,64]
{
    __shared__ __align__(16) float TA_s[7 * 192];
    __shared__ __align__(16) float TAS_s[20 * 192];
    __shared__ __align__(16) float wbet_s[192];
    __shared__ __align__(16) float h_s[SEQ * HID];
    __shared__ __align__(16) float a_s[SEQ * 192];   // gate pre-activations
    __shared__ __align__(16) float hn_s[SEQ * HID];  // hidden-side n-gate term
    __shared__ int   aoff_s[SEQ * TT];
    __shared__ int   coff_s[SEQ * TT];
    __shared__ float bet_s[SEQ * TT];
    __shared__ int   len_s[SEQ];

    const int j = threadIdx.x;          // thread owns rows j and j+96
    const int b = blockIdx.x;           // sequence-group id
    const int rA = j;
    const int rB = j + 96;

    // ---- load tables to shared (vectorized) ----
    {
        const float4* src1 = (const float4*)gTA;
        float4*       dst1 = (float4*)TA_s;
        for (int i = j; i < 7 * 192 / 4; i += NTH) dst1[i] = src1[i];
        const float4* src2 = (const float4*)gTAS;
        float4*       dst2 = (float4*)TAS_s;
        for (int i = j; i < 20 * 192 / 4; i += NTH) dst2[i] = src2[i];
        const float4* src3 = (const float4*)gWbet;
        float4*       dst3 = (float4*)wbet_s;
        for (int i = j; i < 192 / 4; i += NTH) dst3[i] = src3[i];
    }
    if (j < HID) {
        #pragma unroll
        for (int s = 0; s < SEQ; s++) h_s[s * HID + j] = 0.f;
    }

    // ---- per-thread W_hh rows in registers, packed as f32x2 pairs ----
    ulonglong2 whhA[16], whhB[16];
    {
        const ulonglong2* qA = (const ulonglong2*)(W_hh + rA * 64);
        const ulonglong2* qB = (const ulonglong2*)(W_hh + rB * 64);
        #pragma unroll
        for (int i = 0; i < 16; i++) { whhA[i] = qA[i]; whhB[i] = qB[i]; }
    }
    const float bhA = b_hh[rA];
    const float bhB = b_hh[rB];

    // ---- per-seq lengths from prefix-valid mask (int32 words) ----
    int maxlen = 0;
    #pragma unroll
    for (int s = 0; s < SEQ; s++) {
        const int base = (b * SEQ + s) * TT;
        const int c1 = __syncthreads_count(mask[base + j] != 0);
        const int c2 = __syncthreads_count((j < TT - NTH) &&
                                           (mask[base + NTH + j] != 0));
        const int l = c1 + c2;
        if (j == 0) len_s[s] = l;
        maxlen = max(maxlen, l);
    }

    // ---- stage per-step table offsets + bet for all SEQ sequences ----
    {
        const int gbase = b * SEQ * TT;
        for (int i = j; i < SEQ * TT; i += NTH) {
            aoff_s[i] = actor[gbase + i] * 192;
            coff_s[i] = (action[gbase + i] * 5 + street[gbase + i]) * 192;
            bet_s[i]  = bet[gbase + i];
        }
    }
    __syncthreads();

    // ---- recurrent loop over timesteps; SEQ sequences per step ----
    for (int t = 0; t < maxlen; t++) {
        #pragma unroll 2
        for (int s = 0; s < SEQ; s++) {
            if (t < len_s[s]) {          // CTA-uniform branch
                const ulonglong2* hp = (const ulonglong2*)(h_s + s * HID);

                unsigned long long hA0 = 0, hA1 = 0, hA2 = 0, hA3 = 0;
                unsigned long long hB0 = 0, hB1 = 0, hB2 = 0, hB3 = 0;
                #pragma unroll
                for (int i = 0; i < 16; i += 2) {
                    const ulonglong2 h0 = hp[i];
                    const ulonglong2 h1 = hp[i + 1];
                    ffma2(hA0, whhA[i].x,     h0.x);
                    ffma2(hA1, whhA[i].y,     h0.y);
                    ffma2(hA2, whhA[i + 1].x, h1.x);
                    ffma2(hA3, whhA[i + 1].y, h1.y);
                    ffma2(hB0, whhB[i].x,     h0.x);
                    ffma2(hB1, whhB[i].y,     h0.y);
                    ffma2(hB2, whhB[i + 1].x, h1.x);
                    ffma2(hB3, whhB[i + 1].y, h1.y);
                }

                const int   idx = s * TT + t;
                const int   ao  = aoff_s[idx];
                const int   co  = coff_s[idx];
                const float bf  = bet_s[idx];

                const float ghA = bhA + ((red2(hA0) + red2(hA1)) +
                                         (red2(hA2) + red2(hA3)));
                const float ghB = bhB + ((red2(hB0) + red2(hB1)) +
                                         (red2(hB2) + red2(hB3)));
                const float xgA = TA_s[ao + rA] + TAS_s[co + rA] + wbet_s[rA] * bf;
                const float xgB = TA_s[ao + rB] + TAS_s[co + rB] + wbet_s[rB] * bf;

                a_s[s * 192 + rA] = xgA + ghA;
                a_s[s * 192 + rB] = xgB + ghB;
                if (rB >= 128) hn_s[s * HID + rB - 128] = ghB;
            }
        }
        __syncthreads();

        if (j < HID) {
            #pragma unroll 2
            for (int s = 0; s < SEQ; s++) {
                if (t < len_s[s]) {
                    const float* as = a_s + s * 192;
                    const float r  = sigm_fast(as[j]);
                    const float z  = sigm_fast(as[j + 64]);
                    const float hn = hn_s[s * HID + j];
                    // as[j+128] = xn + hn -> xn + r*hn = as + (r-1)*hn
                    const float n  = tanh_fast(as[j + 128] + (r - 1.f) * hn);
                    h_s[s * HID + j] = (1.f - z) * n + z * h_s[s * HID + j];
                }
            }
        }
        __syncthreads();
    }

    if (j < HID) {
        #pragma unroll
        for (int s = 0; s < SEQ; s++)
            out[(long long)(b * SEQ + s) * HID + j] = h_s[s * HID + j];
    }
}

extern "C" void kernel_launch(void* const* d_in, const int* in_sizes, int n_in,
                              void* d_out, int out_size) {
    const int*   actor    = (const int*)  d_in[0];
    const int*   action   = (const int*)  d_in[1];
    const int*   street   = (const int*)  d_in[2];
    const float* bet      = (const float*)d_in[3];
    const int*   mask     = (const int*)  d_in[4];
    const float* E_actor  = (const float*)d_in[5];
    const float* E_action = (const float*)d_in[6];
    const float* E_street = (const float*)d_in[7];
    const float* W_proj   = (const float*)d_in[8];
    const float* b_proj   = (const float*)d_in[9];
    const float* W_ih     = (const float*)d_in[10];
    const float* W_hh     = (const float*)d_in[11];
    const float* b_ih     = (const float*)d_in[12];
    const float* b_hh     = (const float*)d_in[13];
    float*       out      = (float*)      d_out;

    precompute_tables<<<1, 192>>>(E_actor, E_action, E_street,
                                  W_proj, b_proj, W_ih, b_ih);
    gru_seq_kernel<<<BB / SEQ, NTH>>>(actor, action, street, bet, mask,
                                      W_hh, b_hh, out);
}

// round 8
// speedup vs baseline: 1.1890x; 1.1890x over previous
#include <cuda_runtime.h>
#include <cstdint>

#define BB   8192
#define TT   128
#define HID  64
#define NTH  128   // thread pair (2k,2k+1) owns hidden unit k

// Precomputed input-path tables (filled by precompute_tables kernel).
__device__ float gTA[7 * 192];
__device__ float gTAS[20 * 192];
__device__ float gWbet[192];

// Packed fp32x2 FMA: d = a*b + d (FFMA2, only emitted via PTX fma.rn.f32x2)
__device__ __forceinline__ void ffma2(unsigned long long &d,
                                      unsigned long long a,
                                      unsigned long long b) {
    asm("fma.rn.f32x2 %0, %1, %2, %0;" : "+l"(d) : "l"(a), "l"(b));
}
__device__ __forceinline__ float lo32(unsigned long long v) {
    return __uint_as_float((unsigned)v);
}
__device__ __forceinline__ float hi32(unsigned long long v) {
    return __uint_as_float((unsigned)(v >> 32));
}
__device__ __forceinline__ float red2(unsigned long long v) {
    return lo32(v) + hi32(v);
}

__device__ __forceinline__ float sigm_fast(float x) {
    return __fdividef(1.f, 1.f + __expf(-x));
}
__device__ __forceinline__ float tanh_fast(float x) {
    return 1.f - 2.f * __fdividef(1.f, __expf(2.f * x) + 1.f);
}

// One block of 192 threads; thread r computes row r of all tables.
__global__ void precompute_tables(const float* __restrict__ E_actor,   // [7,8]
                                  const float* __restrict__ E_action,  // [4,8]
                                  const float* __restrict__ E_street,  // [5,4]
                                  const float* __restrict__ W_proj,    // [32,21]
                                  const float* __restrict__ b_proj,    // [32]
                                  const float* __restrict__ W_ih,      // [192,32]
                                  const float* __restrict__ b_ih)      // [192]
{
    const int r = threadIdx.x;   // 0..191
    float M[21];
    #pragma unroll
    for (int c = 0; c < 21; c++) {
        float s = 0.f;
        for (int i = 0; i < 32; i++) s += W_ih[r * 32 + i] * W_proj[i * 21 + c];
        M[c] = s;
    }
    float b0 = b_ih[r];
    for (int i = 0; i < 32; i++) b0 += W_ih[r * 32 + i] * b_proj[i];

    for (int a = 0; a < 7; a++) {
        float s = b0;
        #pragma unroll
        for (int c = 0; c < 8; c++) s += M[c] * E_actor[a * 8 + c];
        gTA[a * 192 + r] = s;
    }
    for (int ac = 0; ac < 4; ac++) {
        float sa = 0.f;
        #pragma unroll
        for (int c = 0; c < 8; c++) sa += M[8 + c] * E_action[ac * 8 + c];
        for (int st = 0; st < 5; st++) {
            float s = sa;
            #pragma unroll
            for (int c = 0; c < 4; c++) s += M[16 + c] * E_street[st * 4 + c];
            gTAS[(ac * 5 + st) * 192 + r] = s;
        }
    }
    gWbet[r] = M[20];
}

__global__ __launch_bounds__(NTH, 3)
void gru_seq_kernel(const int*  __restrict__ actor,
                    const int*  __restrict__ action,
                    const int*  __restrict__ street,
                    const float* __restrict__ bet,
                    const int*  __restrict__ mask,            // bool->int32 [B,T]
                    const float* __restrict__ W_hh,           // [192,64]
                    const float* __restrict__ b_hh,           // [192]
                    float* __restrict__ out)                  // [B,64]
{
    __shared__ __align__(16) float TA_s[7 * 192];
    __shared__ __align__(16) float TAS_s[20 * 192];
    __shared__ __align__(16) float wbet_s[192];
    __shared__ __align__(16) float h_s[2][HID];   // double-buffered hidden
    __shared__ int   aoff_s[TT];
    __shared__ int   coff_s[TT];
    __shared__ float bet_s[TT];

    const int j    = threadIdx.x;
    const int b    = blockIdx.x;        // sequence id
    const int k    = j >> 1;            // hidden unit 0..63
    const int half = j & 1;             // which 32-wide half of the dot
    const int rR = k, rZ = k + 64, rN = k + 128;

    // ---- load tables to shared (vectorized) ----
    {
        const float4* src1 = (const float4*)gTA;
        float4*       dst1 = (float4*)TA_s;
        for (int i = j; i < 7 * 192 / 4; i += NTH) dst1[i] = src1[i];
        const float4* src2 = (const float4*)gTAS;
        float4*       dst2 = (float4*)TAS_s;
        for (int i = j; i < 20 * 192 / 4; i += NTH) dst2[i] = src2[i];
        const float4* src3 = (const float4*)gWbet;
        float4*       dst3 = (float4*)wbet_s;
        for (int i = j; i < 192 / 4; i += NTH) dst3[i] = src3[i];
    }
    if (j < HID) { h_s[0][j] = 0.f; h_s[1][j] = 0.f; }

    // ---- per-thread W_hh half-rows (32 floats = 8 ulonglong2) in registers ----
    ulonglong2 wR[8], wZ[8], wN[8];
    {
        const ulonglong2* pR = (const ulonglong2*)(W_hh + rR * 64 + half * 32);
        const ulonglong2* pZ = (const ulonglong2*)(W_hh + rZ * 64 + half * 32);
        const ulonglong2* pN = (const ulonglong2*)(W_hh + rN * 64 + half * 32);
        #pragma unroll
        for (int i = 0; i < 8; i++) { wR[i] = pR[i]; wZ[i] = pZ[i]; wN[i] = pN[i]; }
    }
    const float bhR = b_hh[rR];
    const float bhZ = b_hh[rZ];
    const float bhN = b_hh[rN];

    // ---- sequence length from prefix-valid mask (int32 words) ----
    // (__syncthreads_count also orders the table fills above)
    const int len = __syncthreads_count(mask[b * TT + j] != 0);

    const float wbR = wbet_s[rR];
    const float wbZ = wbet_s[rZ];
    const float wbN = wbet_s[rN];

    // ---- stage per-step table offsets + bet ----
    for (int t = j; t < len; t += NTH) {
        aoff_s[t] = actor[b * TT + t] * 192;
        coff_s[t] = (action[b * TT + t] * 5 + street[b * TT + t]) * 192;
        bet_s[t]  = bet[b * TT + t];
    }
    __syncthreads();

    // ---- recurrent loop: ONE barrier per step (double-buffered h) ----
    for (int t = 0; t < len; t++) {
        const int rd = t & 1, wr = rd ^ 1;
        const ulonglong2* hp = (const ulonglong2*)h_s[rd] + half * 8;

        // half-dots for the three gate rows of unit k (2 chains each)
        unsigned long long aR0 = 0, aR1 = 0, aZ0 = 0, aZ1 = 0, aN0 = 0, aN1 = 0;
        #pragma unroll
        for (int i = 0; i < 8; i++) {
            const ulonglong2 hv = hp[i];
            ffma2(aR0, wR[i].x, hv.x);
            ffma2(aR1, wR[i].y, hv.y);
            ffma2(aZ0, wZ[i].x, hv.x);
            ffma2(aZ1, wZ[i].y, hv.y);
            ffma2(aN0, wN[i].x, hv.x);
            ffma2(aN1, wN[i].y, hv.y);
        }
        float pR = red2(aR0) + red2(aR1);
        float pZ = red2(aZ0) + red2(aZ1);
        float pN = red2(aN0) + red2(aN1);

        // merge the two halves of each dot across the thread pair
        pR += __shfl_xor_sync(0xffffffffu, pR, 1);
        pZ += __shfl_xor_sync(0xffffffffu, pZ, 1);
        pN += __shfl_xor_sync(0xffffffffu, pN, 1);

        const int   ao = aoff_s[t];
        const int   co = coff_s[t];
        const float bf = bet_s[t];

        const float xgR = TA_s[ao + rR] + TAS_s[co + rR] + wbR * bf;
        const float xgZ = TA_s[ao + rZ] + TAS_s[co + rZ] + wbZ * bf;
        const float xgN = TA_s[ao + rN] + TAS_s[co + rN] + wbN * bf;

        const float ghN = pN + bhN;                  // hidden n-term incl. bias
        const float r   = sigm_fast(xgR + pR + bhR);
        const float z   = sigm_fast(xgZ + pZ + bhZ);
        const float n   = tanh_fast(xgN + r * ghN);
        const float hk  = h_s[rd][k];
        if (half == 0) h_s[wr][k] = (1.f - z) * n + z * hk;

        __syncthreads();   // write buf visible before next step reads it
    }

    if (j < HID) out[(long long)b * HID + j] = h_s[len & 1][j];
}

extern "C" void kernel_launch(void* const* d_in, const int* in_sizes, int n_in,
                              void* d_out, int out_size) {
    const int*   actor    = (const int*)  d_in[0];
    const int*   action   = (const int*)  d_in[1];
    const int*   street   = (const int*)  d_in[2];
    const float* bet      = (const float*)d_in[3];
    const int*   mask     = (const int*)  d_in[4];
    const float* E_actor  = (const float*)d_in[5];
    const float* E_action = (const float*)d_in[6];
    const float* E_street = (const float*)d_in[7];
    const float* W_proj   = (const float*)d_in[8];
    const float* b_proj   = (const float*)d_in[9];
    const float* W_ih     = (const float*)d_in[10];
    const float* W_hh     = (const float*)d_in[11];
    const float* b_ih     = (const float*)d_in[12];
    const float* b_hh     = (const float*)d_in[13];
    float*       out      = (float*)      d_out;

    precompute_tables<<<1, 192>>>(E_actor, E_action, E_street,
                                  W_proj, b_proj, W_ih, b_ih);
    gru_seq_kernel<<<BB, NTH>>>(actor, action, street, bet, mask,
                                W_hh, b_hh, out);
}